// round 13
// baseline (speedup 1.0000x reference)
#include <cuda_runtime.h>

// Pooling_83141976916902: out[g, c] = sum_{i : batch[i]==g} x[i, c]
// (softmax over a size-1 axis == 1.0, so W/b are dead inputs)
//
// x:     [N, 128] float32   (d_in[0])
// batch: [N]      int64/int32, SORTED, values in [0, G)  (d_in[1])
// out:   [G, 128] float32
//
// FINAL (R8 body, best measured: 76.3us total; kernel 75.7us =
// 525MB compulsory traffic / 6.94TB/s achieved = 86.7% of spec HBM).
//   - 32 rows/warp, 8 warps/block (empirically pinned optimum; 64-row
//     stripes regress at any grid shape)
//   - segment ids hoisted to registers once per stripe, shfl broadcast
//   - 8-deep front-batched evict-first LDG.128 x stream
//   - red.global.add.v4.f32 (REDG.128) flush only on segment change
//   - graph memset node zeroes the poisoned output
//   - in-kernel dtype probe (int64 vs int32 batch), one L2-hit load/block

#define C 128
#define WARPS_PER_BLOCK 8
#define ROWS_PER_WARP 32
#define ROWS_PER_BLOCK (WARPS_PER_BLOCK * ROWS_PER_WARP)  // 256

// One vector reduction (REDG.128, no return) per lane. 16B-aligned by
// construction: out + seg*512B + lane*16B.
__device__ __forceinline__ void flush_acc(float* __restrict__ out, int seg,
                                          int lane, float4& acc) {
    float* o = out + (size_t)seg * C + lane * 4;
    asm volatile("red.global.add.v4.f32 [%0], {%1, %2, %3, %4};"
                 :: "l"(o), "f"(acc.x), "f"(acc.y), "f"(acc.z), "f"(acc.w)
                 : "memory");
    acc = make_float4(0.f, 0.f, 0.f, 0.f);
}

// Segmented sum. One warp owns 32 contiguous rows. Lane l holds channels
// [4l,4l+4) as a float4 accumulator (one coalesced 512B row read). Segment
// ids are loaded ONCE per stripe into registers (one per lane) and broadcast
// per-row via shfl; x rows are loaded in front-batched groups of 8
// independent LDG.128 (streaming, evict-first) before any flush logic.
__global__ __launch_bounds__(ROWS_PER_BLOCK)
void segsum_kernel(const float4* __restrict__ x4,
                   const void* __restrict__ batch_raw,
                   float* __restrict__ out,
                   int n_rows) {
    const int warp = threadIdx.x >> 5;
    const int lane = threadIdx.x & 31;
    const int rstart = blockIdx.x * ROWS_PER_BLOCK + warp * ROWS_PER_WARP;
    if (rstart >= n_rows) return;

    // In-kernel dtype probe: highest ODD 32-bit word of the batch buffer.
    // int64 (values < 2^31): odd words are high halves -> 0.
    // int32: that word is a sorted id near the end (~G-1) -> nonzero.
    // Broadcast L2/L1-hit load: effectively free per block.
    const int* __restrict__ bwords = (const int*)batch_raw;
    int pidx = ((n_rows - 1) & 1) ? (n_rows - 1) : (n_rows - 2);
    if (pidx < 0) pidx = 0;
    const bool is64 = (__ldg(&bwords[pidx]) == 0);

    const long long* __restrict__ b64 = (const long long*)batch_raw;
    const int* __restrict__ b32 = (const int*)batch_raw;

    float4 acc = make_float4(0.f, 0.f, 0.f, 0.f);

    if (rstart + ROWS_PER_WARP <= n_rows) {
        // ---- fast path: full 32-row stripe (always taken when N % 32 == 0) ----
        const int r_lane = rstart + lane;
        int my_id = is64 ? (int)b64[r_lane] : b32[r_lane];

        const float4* __restrict__ p = x4 + (size_t)rstart * (C / 4) + lane;
        int cur = __shfl_sync(0xFFFFFFFFu, my_id, 0);

#pragma unroll
        for (int g = 0; g < ROWS_PER_WARP / 8; g++) {
            // front-batch 8 independent 16B streaming loads (MLP_p1 = 8)
            float4 v0 = __ldcs(p + (g * 8 + 0) * (C / 4));
            float4 v1 = __ldcs(p + (g * 8 + 1) * (C / 4));
            float4 v2 = __ldcs(p + (g * 8 + 2) * (C / 4));
            float4 v3 = __ldcs(p + (g * 8 + 3) * (C / 4));
            float4 v4 = __ldcs(p + (g * 8 + 4) * (C / 4));
            float4 v5 = __ldcs(p + (g * 8 + 5) * (C / 4));
            float4 v6 = __ldcs(p + (g * 8 + 6) * (C / 4));
            float4 v7 = __ldcs(p + (g * 8 + 7) * (C / 4));

            float4 vv[8] = {v0, v1, v2, v3, v4, v5, v6, v7};
#pragma unroll
            for (int j = 0; j < 8; j++) {
                const int s = __shfl_sync(0xFFFFFFFFu, my_id, g * 8 + j);
                if (s != cur) {
                    flush_acc(out, cur, lane, acc);
                    cur = s;
                }
                acc.x += vv[j].x;
                acc.y += vv[j].y;
                acc.z += vv[j].z;
                acc.w += vv[j].w;
            }
        }
        flush_acc(out, cur, lane, acc);
    } else {
        // ---- generic tail path ----
        const int rend = n_rows;
        int cur = is64 ? (int)b64[rstart] : b32[rstart];
        for (int r = rstart; r < rend; r++) {
            const int s = is64 ? (int)b64[r] : b32[r];
            const float4 v = __ldcs(x4 + (size_t)r * (C / 4) + lane);
            if (s != cur) {
                flush_acc(out, cur, lane, acc);
                cur = s;
            }
            acc.x += v.x;
            acc.y += v.y;
            acc.z += v.z;
            acc.w += v.w;
        }
        flush_acc(out, cur, lane, acc);
    }
}

extern "C" void kernel_launch(void* const* d_in, const int* in_sizes, int n_in,
                              void* d_out, int out_size) {
    const float* x = (const float*)d_in[0];
    const void* batch = d_in[1];
    (void)n_in;

    const int n_rows = in_sizes[1];

    // Zero the poisoned output: graph-capturable memset node (no alloc,
    // no sync).
    cudaMemsetAsync(d_out, 0, (size_t)out_size * sizeof(float), 0);

    int blocks = (n_rows + ROWS_PER_BLOCK - 1) / ROWS_PER_BLOCK;
    segsum_kernel<<<blocks, ROWS_PER_BLOCK>>>(
        (const float4*)x, batch, (float*)d_out, n_rows);
}

// round 15
// speedup vs baseline: 1.0227x; 1.0227x over previous
#include <cuda_runtime.h>

// Pooling_83141976916902: out[g, c] = sum_{i : batch[i]==g} x[i, c]
// (softmax over a size-1 axis == 1.0, so W/b are dead inputs)
//
// x:     [N, 128] float32   (d_in[0])
// batch: [N]      int64/int32, SORTED, values in [0, G)  (d_in[1])
// out:   [G, 128] float32
//
// FINAL (R8 body; best measured 76.3us, run-to-run noise +/-1.5us).
// Kernel time == 525MB compulsory traffic / ~6.9TB/s achieved (86% of
// spec HBM) -> at the memory wall.
//   - 32 rows/warp, 8 warps/block (empirically pinned optimum; 64-row
//     stripes regress at any grid shape)
//   - segment ids hoisted to registers once per stripe, shfl broadcast
//   - 8-deep front-batched evict-first LDG.128 x stream
//   - red.global.add.v4.f32 (REDG.128) flush only on segment change
//   - graph memset node zeroes the poisoned output
//   - in-kernel dtype probe (int64 vs int32 batch), one L2-hit load/block

#define C 128
#define WARPS_PER_BLOCK 8
#define ROWS_PER_WARP 32
#define ROWS_PER_BLOCK (WARPS_PER_BLOCK * ROWS_PER_WARP)  // 256

// One vector reduction (REDG.128, no return) per lane. 16B-aligned by
// construction: out + seg*512B + lane*16B.
__device__ __forceinline__ void flush_acc(float* __restrict__ out, int seg,
                                          int lane, float4& acc) {
    float* o = out + (size_t)seg * C + lane * 4;
    asm volatile("red.global.add.v4.f32 [%0], {%1, %2, %3, %4};"
                 :: "l"(o), "f"(acc.x), "f"(acc.y), "f"(acc.z), "f"(acc.w)
                 : "memory");
    acc = make_float4(0.f, 0.f, 0.f, 0.f);
}

// Segmented sum. One warp owns 32 contiguous rows. Lane l holds channels
// [4l,4l+4) as a float4 accumulator (one coalesced 512B row read). Segment
// ids are loaded ONCE per stripe into registers (one per lane) and broadcast
// per-row via shfl; x rows are loaded in front-batched groups of 8
// independent LDG.128 (streaming, evict-first) before any flush logic.
__global__ __launch_bounds__(ROWS_PER_BLOCK)
void segsum_kernel(const float4* __restrict__ x4,
                   const void* __restrict__ batch_raw,
                   float* __restrict__ out,
                   int n_rows) {
    const int warp = threadIdx.x >> 5;
    const int lane = threadIdx.x & 31;
    const int rstart = blockIdx.x * ROWS_PER_BLOCK + warp * ROWS_PER_WARP;
    if (rstart >= n_rows) return;

    // In-kernel dtype probe: highest ODD 32-bit word of the batch buffer.
    // int64 (values < 2^31): odd words are high halves -> 0.
    // int32: that word is a sorted id near the end (~G-1) -> nonzero.
    // Broadcast L2/L1-hit load: effectively free per block.
    const int* __restrict__ bwords = (const int*)batch_raw;
    int pidx = ((n_rows - 1) & 1) ? (n_rows - 1) : (n_rows - 2);
    if (pidx < 0) pidx = 0;
    const bool is64 = (__ldg(&bwords[pidx]) == 0);

    const long long* __restrict__ b64 = (const long long*)batch_raw;
    const int* __restrict__ b32 = (const int*)batch_raw;

    float4 acc = make_float4(0.f, 0.f, 0.f, 0.f);

    if (rstart + ROWS_PER_WARP <= n_rows) {
        // ---- fast path: full 32-row stripe (always taken when N % 32 == 0) ----
        const int r_lane = rstart + lane;
        int my_id = is64 ? (int)b64[r_lane] : b32[r_lane];

        const float4* __restrict__ p = x4 + (size_t)rstart * (C / 4) + lane;
        int cur = __shfl_sync(0xFFFFFFFFu, my_id, 0);

#pragma unroll
        for (int g = 0; g < ROWS_PER_WARP / 8; g++) {
            // front-batch 8 independent 16B streaming loads (MLP_p1 = 8)
            float4 v0 = __ldcs(p + (g * 8 + 0) * (C / 4));
            float4 v1 = __ldcs(p + (g * 8 + 1) * (C / 4));
            float4 v2 = __ldcs(p + (g * 8 + 2) * (C / 4));
            float4 v3 = __ldcs(p + (g * 8 + 3) * (C / 4));
            float4 v4 = __ldcs(p + (g * 8 + 4) * (C / 4));
            float4 v5 = __ldcs(p + (g * 8 + 5) * (C / 4));
            float4 v6 = __ldcs(p + (g * 8 + 6) * (C / 4));
            float4 v7 = __ldcs(p + (g * 8 + 7) * (C / 4));

            float4 vv[8] = {v0, v1, v2, v3, v4, v5, v6, v7};
#pragma unroll
            for (int j = 0; j < 8; j++) {
                const int s = __shfl_sync(0xFFFFFFFFu, my_id, g * 8 + j);
                if (s != cur) {
                    flush_acc(out, cur, lane, acc);
                    cur = s;
                }
                acc.x += vv[j].x;
                acc.y += vv[j].y;
                acc.z += vv[j].z;
                acc.w += vv[j].w;
            }
        }
        flush_acc(out, cur, lane, acc);
    } else {
        // ---- generic tail path ----
        const int rend = n_rows;
        int cur = is64 ? (int)b64[rstart] : b32[rstart];
        for (int r = rstart; r < rend; r++) {
            const int s = is64 ? (int)b64[r] : b32[r];
            const float4 v = __ldcs(x4 + (size_t)r * (C / 4) + lane);
            if (s != cur) {
                flush_acc(out, cur, lane, acc);
                cur = s;
            }
            acc.x += v.x;
            acc.y += v.y;
            acc.z += v.z;
            acc.w += v.w;
        }
        flush_acc(out, cur, lane, acc);
    }
}

extern "C" void kernel_launch(void* const* d_in, const int* in_sizes, int n_in,
                              void* d_out, int out_size) {
    const float* x = (const float*)d_in[0];
    const void* batch = d_in[1];
    (void)n_in;

    const int n_rows = in_sizes[1];

    // Zero the poisoned output: graph-capturable memset node (no alloc,
    // no sync).
    cudaMemsetAsync(d_out, 0, (size_t)out_size * sizeof(float), 0);

    int blocks = (n_rows + ROWS_PER_BLOCK - 1) / ROWS_PER_BLOCK;
    segsum_kernel<<<blocks, ROWS_PER_BLOCK>>>(
        (const float4*)x, batch, (float*)d_out, n_rows);
}